// round 14
// baseline (speedup 1.0000x reference)
#include <cuda_runtime.h>
#include <cuda_bf16.h>
#include <cuda_fp16.h>
#include <cstdint>

// R14: builds on the phase-ordered kernel (measured 718.0us; phase ordering
// was ~neutral -> GEMM is at the fallback-IMMA floor ~515us). This round
// attacks the glue: xT_kernel and g_xT are REMOVED; the scan reconstructs
// x from the int8 digits directly via a per-chunk smem-transposed tile load
// (bit-identical values to what xT produced). Saves one launch + ~160MB of
// pure layout-change traffic.

// ---------------------------------------------------------------------------
// Problem constants
// ---------------------------------------------------------------------------
#define BSZ     2
#define SEQLEN  4096
#define DIM     2048
#define MDIM    (BSZ * SEQLEN)    // 8192
#define KDIM    DIM               // 2048
#define NDIM    (2 * DIM)         // 4096  (W_ig rows ++ W_a rows)
#define NCHUNK  64
#define CHUNK   (SEQLEN / NCHUNK) // 64
#define QSCALE  16256.0f          // 127*128

// ---------------------------------------------------------------------------
// Device-global scratch (no allocations allowed)
// ---------------------------------------------------------------------------
__device__ int8_t g_a1[(size_t)MDIM * KDIM];
__device__ int8_t g_a2[(size_t)MDIM * KDIM];
__device__ int8_t g_b1[(size_t)NDIM * KDIM];
__device__ int8_t g_b2[(size_t)NDIM * KDIM];
__device__ float  g_sA[MDIM];
__device__ float  g_sB[NDIM];
__device__ __half g_LTh[(size_t)NDIM * MDIM];  // logits transposed [n][m], fp16

// ---------------------------------------------------------------------------
// Helpers
// ---------------------------------------------------------------------------
static __device__ __forceinline__ uint32_t smem_u32(const void* p) {
    uint32_t a;
    asm("{ .reg .u64 t; cvta.to.shared.u64 t, %1; cvt.u32.u64 %0, t; }"
        : "=r"(a) : "l"(p));
    return a;
}

static __device__ __forceinline__ void ldsm4(uint32_t& r0, uint32_t& r1,
                                             uint32_t& r2, uint32_t& r3,
                                             uint32_t addr) {
    asm volatile("ldmatrix.sync.aligned.m8n8.x4.shared.b16 {%0,%1,%2,%3}, [%4];"
                 : "=r"(r0), "=r"(r1), "=r"(r2), "=r"(r3) : "r"(addr));
}

// s8 m16n8k32 MMA, s32 accumulate (baseline PTX, sm_80+)
static __device__ __forceinline__ void mma_s8(
    int& c0, int& c1, int& c2, int& c3,
    uint32_t a0, uint32_t a1, uint32_t a2, uint32_t a3,
    uint32_t b0, uint32_t b1) {
    asm volatile(
        "mma.sync.aligned.m16n8k32.row.col.s32.s8.s8.s32 "
        "{%0,%1,%2,%3}, {%4,%5,%6,%7}, {%8,%9}, {%0,%1,%2,%3};"
        : "+r"(c0), "+r"(c1), "+r"(c2), "+r"(c3)
        : "r"(a0), "r"(a1), "r"(a2), "r"(a3), "r"(b0), "r"(b1));
}

// ---------------------------------------------------------------------------
// Quantization: v -> s*(128*d1 + d2), d1 in [-127,127], d2 in [-64,64]
// ---------------------------------------------------------------------------
static __device__ __forceinline__ void quant2(float v, float inv, int8_t& d1, int8_t& d2) {
    float q  = v * inv;
    float t  = rintf(q * 0.0078125f);
    t = fmaxf(-127.f, fminf(127.f, t));
    d1 = (int8_t)(int)t;
    d2 = (int8_t)(int)rintf(q - 128.f * t);
}

// ---------------------------------------------------------------------------
// Kernel 1 (merged): blocks [0, MDIM) do causal conv + quantize A;
//                    blocks [MDIM, MDIM+NDIM) quantize W (W_ig ++ W_a).
// ---------------------------------------------------------------------------
__global__ void __launch_bounds__(256) quant_kernel(
    const float* __restrict__ x, const float* __restrict__ cw,
    const float* __restrict__ wig, const float* __restrict__ wag) {
    __shared__ float red[8];
    int tid = threadIdx.x;
    int wid = tid >> 5, lane = tid & 31;

    float v[2][4];
    float lmax = 0.f;
    if (blockIdx.x < MDIM) {
        int m = blockIdx.x;
        int s = m & (SEQLEN - 1);
#pragma unroll
        for (int qi = 0; qi < 2; ++qi) {
            int q  = tid + qi * 256;     // quad index 0..511
            int d0 = q * 4;
            float4 w0 = *reinterpret_cast<const float4*>(cw + (size_t)(d0 + 0) * 4);
            float4 w1 = *reinterpret_cast<const float4*>(cw + (size_t)(d0 + 1) * 4);
            float4 w2 = *reinterpret_cast<const float4*>(cw + (size_t)(d0 + 2) * 4);
            float4 w3 = *reinterpret_cast<const float4*>(cw + (size_t)(d0 + 3) * 4);
            float a0 = 0.f, a1 = 0.f, a2 = 0.f, a3 = 0.f;
#pragma unroll
            for (int k = 0; k < 4; ++k) {
                if (s - 3 + k >= 0) {
                    float4 xv = reinterpret_cast<const float4*>(x)[(size_t)(m - 3 + k) * (DIM / 4) + q];
                    a0 = fmaf(xv.x, (&w0.x)[k], a0);
                    a1 = fmaf(xv.y, (&w1.x)[k], a1);
                    a2 = fmaf(xv.z, (&w2.x)[k], a2);
                    a3 = fmaf(xv.w, (&w3.x)[k], a3);
                }
            }
            v[qi][0] = a0; v[qi][1] = a1; v[qi][2] = a2; v[qi][3] = a3;
            lmax = fmaxf(lmax, fmaxf(fmaxf(fabsf(a0), fabsf(a1)), fmaxf(fabsf(a2), fabsf(a3))));
        }
    } else {
        int n = blockIdx.x - MDIM;
        const float* src = (n < DIM) ? (wig + (size_t)n * KDIM)
                                     : (wag + (size_t)(n - DIM) * KDIM);
#pragma unroll
        for (int qi = 0; qi < 2; ++qi) {
            int q = tid + qi * 256;
            float4 xv = reinterpret_cast<const float4*>(src)[q];
            v[qi][0] = xv.x; v[qi][1] = xv.y; v[qi][2] = xv.z; v[qi][3] = xv.w;
            lmax = fmaxf(lmax, fmaxf(fmaxf(fabsf(xv.x), fabsf(xv.y)),
                                     fmaxf(fabsf(xv.z), fabsf(xv.w))));
        }
    }
#pragma unroll
    for (int off = 16; off > 0; off >>= 1)
        lmax = fmaxf(lmax, __shfl_xor_sync(0xFFFFFFFFu, lmax, off));
    if (lane == 0) red[wid] = lmax;
    __syncthreads();
    float maxv = red[0];
#pragma unroll
    for (int w = 1; w < 8; ++w) maxv = fmaxf(maxv, red[w]);
    maxv = fmaxf(maxv, 1e-30f);
    float inv = QSCALE / maxv;

    int8_t* dst1;
    int8_t* dst2;
    if (blockIdx.x < MDIM) {
        int m = blockIdx.x;
        if (tid == 0) g_sA[m] = maxv / QSCALE;
        dst1 = g_a1 + (size_t)m * KDIM;
        dst2 = g_a2 + (size_t)m * KDIM;
    } else {
        int n = blockIdx.x - MDIM;
        if (tid == 0) g_sB[n] = maxv / QSCALE;
        dst1 = g_b1 + (size_t)n * KDIM;
        dst2 = g_b2 + (size_t)n * KDIM;
    }
#pragma unroll
    for (int qi = 0; qi < 2; ++qi) {
        int d0 = (tid + qi * 256) * 4;
        int8_t d1v[4], d2v[4];
#pragma unroll
        for (int j = 0; j < 4; ++j) quant2(v[qi][j], inv, d1v[j], d2v[j]);
        *reinterpret_cast<char4*>(dst1 + d0) = make_char4(d1v[0], d1v[1], d1v[2], d1v[3]);
        *reinterpret_cast<char4*>(dst2 + d0) = make_char4(d2v[0], d2v[1], d2v[2], d2v[3]);
    }
}

// ---------------------------------------------------------------------------
// Kernel 2: int8 two-digit GEMM, phase-ordered MMA emission (best known).
// ---------------------------------------------------------------------------
#define TILE_BYTES  16384                 // 128 rows x 128B
#define STAGE_BYTES (4 * TILE_BYTES)      // a1, a2, b1, b2
#define GEMM_SMEM   (3 * STAGE_BYTES)
#define NKT         (KDIM / 128)          // 16 K-iterations

static __device__ __forceinline__ void gemm_issue_loads(
    uint32_t tiles, int slot, int kt, int tid,
    const int8_t* a1, const int8_t* a2,
    const int8_t* b1, const int8_t* b2) {
    uint32_t sb = tiles + (uint32_t)slot * STAGE_BYTES;
#pragma unroll
    for (int t = 0; t < 4; ++t) {
        const int8_t* sp = (t == 0) ? a1 : (t == 1) ? a2 : (t == 2) ? b1 : b2;
        uint32_t tb = sb + (uint32_t)t * TILE_BYTES;
#pragma unroll
        for (int i = 0; i < 4; ++i) {
            int w = tid + i * 256;
            int r = w >> 3, c = w & 7;                 // row 0..127, 16B chunk 0..7
            uint32_t off = (uint32_t)(r * 128 + c * 16);
            uint32_t dst = tb + (off ^ ((off >> 3) & 0x70));
            const int8_t* src = sp + (size_t)r * KDIM + (size_t)kt * 128 + c * 16;
            asm volatile("cp.async.cg.shared.global [%0], [%1], 16;"
                         :: "r"(dst), "l"(__cvta_generic_to_global((void*)src)));
        }
    }
    asm volatile("cp.async.commit_group;" ::: "memory");
}

__global__ void __launch_bounds__(256, 1) gemm_kernel() {
    extern __shared__ __align__(1024) char smraw[];
    uint32_t tiles = smem_u32(smraw);
    int tid = threadIdx.x, wid = tid >> 5, lane = tid & 31;
    int g = lane >> 2, t = lane & 3;
    int warp_m = wid >> 1, warp_n = wid & 1;
    int n0 = blockIdx.x * 128, m0 = blockIdx.y * 128;

    const int8_t* pa1 = g_a1 + (size_t)m0 * KDIM;
    const int8_t* pa2 = g_a2 + (size_t)m0 * KDIM;
    const int8_t* pb1 = g_b1 + (size_t)n0 * KDIM;
    const int8_t* pb2 = g_b2 + (size_t)n0 * KDIM;

    uint32_t a_row  = (uint32_t)(warp_m * 32 + (lane & 15));
    uint32_t a_xor  = (a_row & 7) << 4;
    uint32_t a_half = (uint32_t)((lane >> 4) << 4);           // 0 / 16
    uint32_t b_row  = (uint32_t)(warp_n * 64 + ((lane >> 4) << 3) + (lane & 7));
    uint32_t b_xor  = (b_row & 7) << 4;
    uint32_t b_half = (uint32_t)(((lane >> 3) & 1) << 4);     // 0 / 16

    int acc1[2][8][4], acc2[2][8][4];
#pragma unroll
    for (int mt = 0; mt < 2; ++mt)
#pragma unroll
        for (int nt = 0; nt < 8; ++nt)
#pragma unroll
            for (int r = 0; r < 4; ++r) { acc1[mt][nt][r] = 0; acc2[mt][nt][r] = 0; }

    gemm_issue_loads(tiles, 0, 0, tid, pa1, pa2, pb1, pb2);
    gemm_issue_loads(tiles, 1, 1, tid, pa1, pa2, pb1, pb2);

#pragma unroll 1
    for (int kt = 0; kt < NKT; ++kt) {
        if (kt < NKT - 1) asm volatile("cp.async.wait_group 1;" ::: "memory");
        else              asm volatile("cp.async.wait_group 0;" ::: "memory");
        __syncthreads();
        if (kt + 2 < NKT)
            gemm_issue_loads(tiles, (kt + 2) % 3, kt + 2, tid, pa1, pa2, pb1, pb2);

        int slot = kt % 3;
        uint32_t sb   = tiles + (uint32_t)slot * STAGE_BYTES;
        uint32_t t_a1 = sb;
        uint32_t t_a2 = sb + TILE_BYTES;
        uint32_t t_b1 = sb + 2 * TILE_BYTES;
        uint32_t t_b2 = sb + 3 * TILE_BYTES;

#pragma unroll
        for (int ks = 0; ks < 4; ++ks) {
            uint32_t acol = (uint32_t)(ks * 32);
            uint32_t A1[2][4], A2[2][4];
#pragma unroll
            for (int mt = 0; mt < 2; ++mt) {
                uint32_t ro = (a_row + mt * 16) * 128 + ((acol + a_half) ^ a_xor);
                ldsm4(A1[mt][0], A1[mt][1], A1[mt][2], A1[mt][3], t_a1 + ro);
                ldsm4(A2[mt][0], A2[mt][1], A2[mt][2], A2[mt][3], t_a2 + ro);
            }
#pragma unroll
            for (int prp = 0; prp < 2; ++prp) {
                uint32_t B1[2][4], B2[2][4];
#pragma unroll
                for (int pq = 0; pq < 2; ++pq) {
                    int pr = prp * 2 + pq;
                    uint32_t ro = (b_row + pr * 16) * 128 + ((acol + b_half) ^ b_xor);
                    ldsm4(B1[pq][0], B1[pq][1], B1[pq][2], B1[pq][3], t_b1 + ro);
                    ldsm4(B2[pq][0], B2[pq][1], B2[pq][2], B2[pq][3], t_b2 + ro);
                }
                // phase 1: c1 += A1*B1
#pragma unroll
                for (int pq = 0; pq < 2; ++pq)
#pragma unroll
                    for (int h = 0; h < 2; ++h)
#pragma unroll
                        for (int mt = 0; mt < 2; ++mt) {
                            int* c = acc1[mt][prp * 4 + pq * 2 + h];
                            mma_s8(c[0], c[1], c[2], c[3],
                                   A1[mt][0], A1[mt][1], A1[mt][2], A1[mt][3],
                                   B1[pq][h * 2], B1[pq][h * 2 + 1]);
                        }
                // phase 2: c2 += A1*B2
#pragma unroll
                for (int pq = 0; pq < 2; ++pq)
#pragma unroll
                    for (int h = 0; h < 2; ++h)
#pragma unroll
                        for (int mt = 0; mt < 2; ++mt) {
                            int* c = acc2[mt][prp * 4 + pq * 2 + h];
                            mma_s8(c[0], c[1], c[2], c[3],
                                   A1[mt][0], A1[mt][1], A1[mt][2], A1[mt][3],
                                   B2[pq][h * 2], B2[pq][h * 2 + 1]);
                        }
                // phase 3: c2 += A2*B1
#pragma unroll
                for (int pq = 0; pq < 2; ++pq)
#pragma unroll
                    for (int h = 0; h < 2; ++h)
#pragma unroll
                        for (int mt = 0; mt < 2; ++mt) {
                            int* c = acc2[mt][prp * 4 + pq * 2 + h];
                            mma_s8(c[0], c[1], c[2], c[3],
                                   A2[mt][0], A2[mt][1], A2[mt][2], A2[mt][3],
                                   B1[pq][h * 2], B1[pq][h * 2 + 1]);
                        }
            }
        }
    }

    // Epilogue: logit = sA*sB*(16384*acc1 + 128*acc2) -> g_LTh[n][m] (fp16)
    float sAv[4];
#pragma unroll
    for (int mt = 0; mt < 2; ++mt)
#pragma unroll
        for (int h = 0; h < 2; ++h)
            sAv[mt * 2 + h] = g_sA[m0 + warp_m * 32 + mt * 16 + g + h * 8];
    float sBv[16];
#pragma unroll
    for (int nt = 0; nt < 8; ++nt)
#pragma unroll
        for (int j = 0; j < 2; ++j)
            sBv[nt * 2 + j] = g_sB[n0 + warp_n * 64 + nt * 8 + 2 * t + j];

#pragma unroll
    for (int mt = 0; mt < 2; ++mt)
#pragma unroll
        for (int nt = 0; nt < 8; ++nt)
#pragma unroll
            for (int r = 0; r < 4; ++r) {
                int m = m0 + warp_m * 32 + mt * 16 + g + ((r >= 2) ? 8 : 0);
                int n = n0 + warp_n * 64 + nt * 8 + 2 * t + (r & 1);
                float val = sAv[mt * 2 + (r >> 1)] * sBv[nt * 2 + (r & 1)] *
                            fmaf(16384.f, (float)acc1[mt][nt][r],
                                 128.f * (float)acc2[mt][nt][r]);
                g_LTh[(size_t)n * MDIM + m] = __float2half(val);
            }
}

// ---------------------------------------------------------------------------
// Kernel 3: gates + linear recurrence. The x tile is reconstructed from the
//   int8 digits per chunk via a cooperative smem-transposed load (replaces
//   the former xT kernel; values are bit-identical).
//   Per chunk: tile-load -> sync -> compute+stage -> sync -> drain.
// ---------------------------------------------------------------------------
static __device__ __forceinline__ float fast_sigmoid(float x) {
    return __fdividef(1.0f, 1.0f + __expf(-x));
}

__global__ void __launch_bounds__(1024, 1) scan_kernel(
    const float* __restrict__ a_param,
    const int* __restrict__ cu, int ncu,
    float* __restrict__ out) {
    __shared__ float sm[CHUNK * 33];      // output staging
    __shared__ float xs[32][CHUNK + 1];   // transposed x tile [dd][t]
    int tid = threadIdx.x;
    int wid = tid >> 5, lane = tid & 31;
    int dgroup = blockIdx.x, b = blockIdx.y;
    int d = dgroup * 32 + wid;

    const __half* rowLx = g_LTh + (size_t)d * MDIM + (size_t)b * SEQLEN;
    const __half* rowLa = g_LTh + (size_t)(DIM + d) * MDIM + (size_t)b * SEQLEN;
    float af = log1pf(__expf(a_param[d & 127]));      // softplus, tiled over heads

    float h = 0.0f;
#pragma unroll 1
    for (int c = 0; c < NCHUNK; ++c) {
        int s0 = c * CHUNK + lane * 2;

        // --- cooperative digit-tile load: rows m = b*SEQLEN + c*64 + t,
        //     cols d = dgroup*32 + dd; consecutive tid -> consecutive dd ---
#pragma unroll
        for (int rep = 0; rep < 2; ++rep) {
            int idx = tid + rep * 1024;               // 0..2047
            int tt = idx >> 5, dd = idx & 31;
            int mrow = b * SEQLEN + c * CHUNK + tt;
            size_t gidx = (size_t)mrow * KDIM + dgroup * 32 + dd;
            float sA = g_sA[mrow];
            xs[dd][tt] = sA * fmaf(128.f, (float)g_a1[gidx], (float)g_a2[gidx]);
        }
        __syncthreads();

        float2 lx = __half22float2(*reinterpret_cast<const __half2*>(rowLx + s0));
        float2 la = __half22float2(*reinterpret_cast<const __half2*>(rowLa + s0));
        float xv0 = xs[wid][lane * 2];
        float xv1 = xs[wid][lane * 2 + 1];

        float A0, B0, A1, B1;
        {
            float gx = fast_sigmoid(lx.x);
            float ga = fast_sigmoid(la.x);
            float a  = __expf(-8.0f * ga * af);
            float mult = sqrtf(fmaxf(1.0f - a * a, 0.0f));
            B0 = mult * gx * xv0;
            A0 = a;
            for (int j = 0; j < ncu - 1; ++j) if (s0 == cu[j]) A0 = 0.0f;
        }
        {
            float gx = fast_sigmoid(lx.y);
            float ga = fast_sigmoid(la.y);
            float a  = __expf(-8.0f * ga * af);
            float mult = sqrtf(fmaxf(1.0f - a * a, 0.0f));
            B1 = mult * gx * xv1;
            A1 = a;
            for (int j = 0; j < ncu - 1; ++j) if (s0 + 1 == cu[j]) A1 = 0.0f;
        }

        float Ai = A0 * A1;
        float Bi = fmaf(A1, B0, B1);
#pragma unroll
        for (int off = 1; off < 32; off <<= 1) {
            float pa = __shfl_up_sync(0xFFFFFFFFu, Ai, off);
            float pb = __shfl_up_sync(0xFFFFFFFFu, Bi, off);
            if (lane >= off) { Bi = fmaf(Ai, pb, Bi); Ai = Ai * pa; }
        }
        float Ae = __shfl_up_sync(0xFFFFFFFFu, Ai, 1);
        float Be = __shfl_up_sync(0xFFFFFFFFu, Bi, 1);
        if (lane == 0) { Ae = 1.0f; Be = 0.0f; }
        float h_in = fmaf(Ae, h, Be);
        float h0 = fmaf(A0, h_in, B0);
        float h1 = fmaf(A1, h0, B1);
        float At = __shfl_sync(0xFFFFFFFFu, Ai, 31);
        float Bt = __shfl_sync(0xFFFFFFFFu, Bi, 31);
        h = fmaf(At, h, Bt);

        sm[(2 * lane) * 33 + wid]     = h0;
        sm[(2 * lane + 1) * 33 + wid] = h1;
        __syncthreads();
        {
            size_t obase = ((size_t)b * SEQLEN + (size_t)c * CHUNK) * DIM + dgroup * 32;
#pragma unroll
            for (int rep = 0; rep < 2; ++rep) {
                int i = tid + rep * 1024;
                int tt = i >> 5, dd = i & 31;
                out[obase + (size_t)tt * DIM + dd] = sm[tt * 33 + dd];
            }
        }
        // next chunk's tile-load sync also orders these sm reads before the
        // following compute's sm writes, so no extra barrier is needed.
    }
}

// ---------------------------------------------------------------------------
// Launch
// ---------------------------------------------------------------------------
extern "C" void kernel_launch(void* const* d_in, const int* in_sizes, int n_in,
                              void* d_out, int out_size) {
    const float* x    = (const float*)d_in[0];
    const float* cw   = (const float*)d_in[1];
    const float* wig  = (const float*)d_in[2];
    const float* wag  = (const float*)d_in[3];
    const float* ap   = (const float*)d_in[4];
    const int*   cu   = (const int*)d_in[5];
    int ncu = in_sizes[5];
    float* out = (float*)d_out;

    quant_kernel<<<MDIM + NDIM, 256>>>(x, cw, wig, wag);

    cudaFuncSetAttribute(gemm_kernel, cudaFuncAttributeMaxDynamicSharedMemorySize,
                         GEMM_SMEM);
    gemm_kernel<<<dim3(NDIM / 128, MDIM / 128), 256, GEMM_SMEM>>>();

    scan_kernel<<<dim3(DIM / 32, BSZ), 1024>>>(ap, cu, ncu, out);
}

// round 15
// speedup vs baseline: 1.0317x; 1.0317x over previous
#include <cuda_runtime.h>
#include <cuda_bf16.h>
#include <cuda_fp16.h>
#include <cstdint>

// R15: revert R14's in-scan reconstruction (it added 64 latency-exposed
// block barriers to the serial scan path: 718.0 -> 739.3). Restore xT +
// g_xT, and add ONE new change: register software-pipelining in the scan
// (prefetch chunk c+1's lx/la/xv while chunk c's shuffle scan runs).

// ---------------------------------------------------------------------------
// Problem constants
// ---------------------------------------------------------------------------
#define BSZ     2
#define SEQLEN  4096
#define DIM     2048
#define MDIM    (BSZ * SEQLEN)    // 8192
#define KDIM    DIM               // 2048
#define NDIM    (2 * DIM)         // 4096  (W_ig rows ++ W_a rows)
#define NCHUNK  64
#define CHUNK   (SEQLEN / NCHUNK) // 64
#define QSCALE  16256.0f          // 127*128

// ---------------------------------------------------------------------------
// Device-global scratch (no allocations allowed)
// ---------------------------------------------------------------------------
__device__ int8_t g_a1[(size_t)MDIM * KDIM];
__device__ int8_t g_a2[(size_t)MDIM * KDIM];
__device__ int8_t g_b1[(size_t)NDIM * KDIM];
__device__ int8_t g_b2[(size_t)NDIM * KDIM];
__device__ float  g_sA[MDIM];
__device__ float  g_sB[NDIM];
__device__ __half g_LTh[(size_t)NDIM * MDIM];  // logits transposed [n][m], fp16
__device__ float  g_xT[(size_t)DIM  * MDIM];   // conv output transposed [d][m]

// ---------------------------------------------------------------------------
// Helpers
// ---------------------------------------------------------------------------
static __device__ __forceinline__ uint32_t smem_u32(const void* p) {
    uint32_t a;
    asm("{ .reg .u64 t; cvta.to.shared.u64 t, %1; cvt.u32.u64 %0, t; }"
        : "=r"(a) : "l"(p));
    return a;
}

static __device__ __forceinline__ void ldsm4(uint32_t& r0, uint32_t& r1,
                                             uint32_t& r2, uint32_t& r3,
                                             uint32_t addr) {
    asm volatile("ldmatrix.sync.aligned.m8n8.x4.shared.b16 {%0,%1,%2,%3}, [%4];"
                 : "=r"(r0), "=r"(r1), "=r"(r2), "=r"(r3) : "r"(addr));
}

// s8 m16n8k32 MMA, s32 accumulate (baseline PTX, sm_80+)
static __device__ __forceinline__ void mma_s8(
    int& c0, int& c1, int& c2, int& c3,
    uint32_t a0, uint32_t a1, uint32_t a2, uint32_t a3,
    uint32_t b0, uint32_t b1) {
    asm volatile(
        "mma.sync.aligned.m16n8k32.row.col.s32.s8.s8.s32 "
        "{%0,%1,%2,%3}, {%4,%5,%6,%7}, {%8,%9}, {%0,%1,%2,%3};"
        : "+r"(c0), "+r"(c1), "+r"(c2), "+r"(c3)
        : "r"(a0), "r"(a1), "r"(a2), "r"(a3), "r"(b0), "r"(b1));
}

// ---------------------------------------------------------------------------
// Quantization: v -> s*(128*d1 + d2), d1 in [-127,127], d2 in [-64,64]
// ---------------------------------------------------------------------------
static __device__ __forceinline__ void quant2(float v, float inv, int8_t& d1, int8_t& d2) {
    float q  = v * inv;
    float t  = rintf(q * 0.0078125f);
    t = fmaxf(-127.f, fminf(127.f, t));
    d1 = (int8_t)(int)t;
    d2 = (int8_t)(int)rintf(q - 128.f * t);
}

// ---------------------------------------------------------------------------
// Kernel 1 (merged): blocks [0, MDIM) do causal conv + quantize A;
//                    blocks [MDIM, MDIM+NDIM) quantize W (W_ig ++ W_a).
// ---------------------------------------------------------------------------
__global__ void __launch_bounds__(256) quant_kernel(
    const float* __restrict__ x, const float* __restrict__ cw,
    const float* __restrict__ wig, const float* __restrict__ wag) {
    __shared__ float red[8];
    int tid = threadIdx.x;
    int wid = tid >> 5, lane = tid & 31;

    float v[2][4];
    float lmax = 0.f;
    if (blockIdx.x < MDIM) {
        int m = blockIdx.x;
        int s = m & (SEQLEN - 1);
#pragma unroll
        for (int qi = 0; qi < 2; ++qi) {
            int q  = tid + qi * 256;     // quad index 0..511
            int d0 = q * 4;
            float4 w0 = *reinterpret_cast<const float4*>(cw + (size_t)(d0 + 0) * 4);
            float4 w1 = *reinterpret_cast<const float4*>(cw + (size_t)(d0 + 1) * 4);
            float4 w2 = *reinterpret_cast<const float4*>(cw + (size_t)(d0 + 2) * 4);
            float4 w3 = *reinterpret_cast<const float4*>(cw + (size_t)(d0 + 3) * 4);
            float a0 = 0.f, a1 = 0.f, a2 = 0.f, a3 = 0.f;
#pragma unroll
            for (int k = 0; k < 4; ++k) {
                if (s - 3 + k >= 0) {
                    float4 xv = reinterpret_cast<const float4*>(x)[(size_t)(m - 3 + k) * (DIM / 4) + q];
                    a0 = fmaf(xv.x, (&w0.x)[k], a0);
                    a1 = fmaf(xv.y, (&w1.x)[k], a1);
                    a2 = fmaf(xv.z, (&w2.x)[k], a2);
                    a3 = fmaf(xv.w, (&w3.x)[k], a3);
                }
            }
            v[qi][0] = a0; v[qi][1] = a1; v[qi][2] = a2; v[qi][3] = a3;
            lmax = fmaxf(lmax, fmaxf(fmaxf(fabsf(a0), fabsf(a1)), fmaxf(fabsf(a2), fabsf(a3))));
        }
    } else {
        int n = blockIdx.x - MDIM;
        const float* src = (n < DIM) ? (wig + (size_t)n * KDIM)
                                     : (wag + (size_t)(n - DIM) * KDIM);
#pragma unroll
        for (int qi = 0; qi < 2; ++qi) {
            int q = tid + qi * 256;
            float4 xv = reinterpret_cast<const float4*>(src)[q];
            v[qi][0] = xv.x; v[qi][1] = xv.y; v[qi][2] = xv.z; v[qi][3] = xv.w;
            lmax = fmaxf(lmax, fmaxf(fmaxf(fabsf(xv.x), fabsf(xv.y)),
                                     fmaxf(fabsf(xv.z), fabsf(xv.w))));
        }
    }
#pragma unroll
    for (int off = 16; off > 0; off >>= 1)
        lmax = fmaxf(lmax, __shfl_xor_sync(0xFFFFFFFFu, lmax, off));
    if (lane == 0) red[wid] = lmax;
    __syncthreads();
    float maxv = red[0];
#pragma unroll
    for (int w = 1; w < 8; ++w) maxv = fmaxf(maxv, red[w]);
    maxv = fmaxf(maxv, 1e-30f);
    float inv = QSCALE / maxv;

    int8_t* dst1;
    int8_t* dst2;
    if (blockIdx.x < MDIM) {
        int m = blockIdx.x;
        if (tid == 0) g_sA[m] = maxv / QSCALE;
        dst1 = g_a1 + (size_t)m * KDIM;
        dst2 = g_a2 + (size_t)m * KDIM;
    } else {
        int n = blockIdx.x - MDIM;
        if (tid == 0) g_sB[n] = maxv / QSCALE;
        dst1 = g_b1 + (size_t)n * KDIM;
        dst2 = g_b2 + (size_t)n * KDIM;
    }
#pragma unroll
    for (int qi = 0; qi < 2; ++qi) {
        int d0 = (tid + qi * 256) * 4;
        int8_t d1v[4], d2v[4];
#pragma unroll
        for (int j = 0; j < 4; ++j) quant2(v[qi][j], inv, d1v[j], d2v[j]);
        *reinterpret_cast<char4*>(dst1 + d0) = make_char4(d1v[0], d1v[1], d1v[2], d1v[3]);
        *reinterpret_cast<char4*>(dst2 + d0) = make_char4(d2v[0], d2v[1], d2v[2], d2v[3]);
    }
}

// ---------------------------------------------------------------------------
// Kernel 2: x_T[d][m] reconstructed from int8 digits (restored from R12)
// ---------------------------------------------------------------------------
__global__ void xT_kernel() {
    __shared__ float tile[32][33];
    int d0 = blockIdx.x * 32, m0 = blockIdx.y * 32;
    int tx = threadIdx.x, ty = threadIdx.y;            // 32 x 8
#pragma unroll
    for (int i = 0; i < 4; ++i) {
        int m = m0 + ty + i * 8;
        size_t idx = (size_t)m * KDIM + d0 + tx;
        float sA = g_sA[m];
        tile[ty + i * 8][tx] = sA * fmaf(128.f, (float)g_a1[idx], (float)g_a2[idx]);
    }
    __syncthreads();
#pragma unroll
    for (int i = 0; i < 4; ++i) {
        int d = d0 + ty + i * 8;
        g_xT[(size_t)d * MDIM + m0 + tx] = tile[tx][ty + i * 8];
    }
}

// ---------------------------------------------------------------------------
// Kernel 3: int8 two-digit GEMM, phase-ordered MMA emission (measured best).
// ---------------------------------------------------------------------------
#define TILE_BYTES  16384                 // 128 rows x 128B
#define STAGE_BYTES (4 * TILE_BYTES)      // a1, a2, b1, b2
#define GEMM_SMEM   (3 * STAGE_BYTES)
#define NKT         (KDIM / 128)          // 16 K-iterations

static __device__ __forceinline__ void gemm_issue_loads(
    uint32_t tiles, int slot, int kt, int tid,
    const int8_t* a1, const int8_t* a2,
    const int8_t* b1, const int8_t* b2) {
    uint32_t sb = tiles + (uint32_t)slot * STAGE_BYTES;
#pragma unroll
    for (int t = 0; t < 4; ++t) {
        const int8_t* sp = (t == 0) ? a1 : (t == 1) ? a2 : (t == 2) ? b1 : b2;
        uint32_t tb = sb + (uint32_t)t * TILE_BYTES;
#pragma unroll
        for (int i = 0; i < 4; ++i) {
            int w = tid + i * 256;
            int r = w >> 3, c = w & 7;                 // row 0..127, 16B chunk 0..7
            uint32_t off = (uint32_t)(r * 128 + c * 16);
            uint32_t dst = tb + (off ^ ((off >> 3) & 0x70));
            const int8_t* src = sp + (size_t)r * KDIM + (size_t)kt * 128 + c * 16;
            asm volatile("cp.async.cg.shared.global [%0], [%1], 16;"
                         :: "r"(dst), "l"(__cvta_generic_to_global((void*)src)));
        }
    }
    asm volatile("cp.async.commit_group;" ::: "memory");
}

__global__ void __launch_bounds__(256, 1) gemm_kernel() {
    extern __shared__ __align__(1024) char smraw[];
    uint32_t tiles = smem_u32(smraw);
    int tid = threadIdx.x, wid = tid >> 5, lane = tid & 31;
    int g = lane >> 2, t = lane & 3;
    int warp_m = wid >> 1, warp_n = wid & 1;
    int n0 = blockIdx.x * 128, m0 = blockIdx.y * 128;

    const int8_t* pa1 = g_a1 + (size_t)m0 * KDIM;
    const int8_t* pa2 = g_a2 + (size_t)m0 * KDIM;
    const int8_t* pb1 = g_b1 + (size_t)n0 * KDIM;
    const int8_t* pb2 = g_b2 + (size_t)n0 * KDIM;

    uint32_t a_row  = (uint32_t)(warp_m * 32 + (lane & 15));
    uint32_t a_xor  = (a_row & 7) << 4;
    uint32_t a_half = (uint32_t)((lane >> 4) << 4);           // 0 / 16
    uint32_t b_row  = (uint32_t)(warp_n * 64 + ((lane >> 4) << 3) + (lane & 7));
    uint32_t b_xor  = (b_row & 7) << 4;
    uint32_t b_half = (uint32_t)(((lane >> 3) & 1) << 4);     // 0 / 16

    int acc1[2][8][4], acc2[2][8][4];
#pragma unroll
    for (int mt = 0; mt < 2; ++mt)
#pragma unroll
        for (int nt = 0; nt < 8; ++nt)
#pragma unroll
            for (int r = 0; r < 4; ++r) { acc1[mt][nt][r] = 0; acc2[mt][nt][r] = 0; }

    gemm_issue_loads(tiles, 0, 0, tid, pa1, pa2, pb1, pb2);
    gemm_issue_loads(tiles, 1, 1, tid, pa1, pa2, pb1, pb2);

#pragma unroll 1
    for (int kt = 0; kt < NKT; ++kt) {
        if (kt < NKT - 1) asm volatile("cp.async.wait_group 1;" ::: "memory");
        else              asm volatile("cp.async.wait_group 0;" ::: "memory");
        __syncthreads();
        if (kt + 2 < NKT)
            gemm_issue_loads(tiles, (kt + 2) % 3, kt + 2, tid, pa1, pa2, pb1, pb2);

        int slot = kt % 3;
        uint32_t sb   = tiles + (uint32_t)slot * STAGE_BYTES;
        uint32_t t_a1 = sb;
        uint32_t t_a2 = sb + TILE_BYTES;
        uint32_t t_b1 = sb + 2 * TILE_BYTES;
        uint32_t t_b2 = sb + 3 * TILE_BYTES;

#pragma unroll
        for (int ks = 0; ks < 4; ++ks) {
            uint32_t acol = (uint32_t)(ks * 32);
            uint32_t A1[2][4], A2[2][4];
#pragma unroll
            for (int mt = 0; mt < 2; ++mt) {
                uint32_t ro = (a_row + mt * 16) * 128 + ((acol + a_half) ^ a_xor);
                ldsm4(A1[mt][0], A1[mt][1], A1[mt][2], A1[mt][3], t_a1 + ro);
                ldsm4(A2[mt][0], A2[mt][1], A2[mt][2], A2[mt][3], t_a2 + ro);
            }
#pragma unroll
            for (int prp = 0; prp < 2; ++prp) {
                uint32_t B1[2][4], B2[2][4];
#pragma unroll
                for (int pq = 0; pq < 2; ++pq) {
                    int pr = prp * 2 + pq;
                    uint32_t ro = (b_row + pr * 16) * 128 + ((acol + b_half) ^ b_xor);
                    ldsm4(B1[pq][0], B1[pq][1], B1[pq][2], B1[pq][3], t_b1 + ro);
                    ldsm4(B2[pq][0], B2[pq][1], B2[pq][2], B2[pq][3], t_b2 + ro);
                }
                // phase 1: c1 += A1*B1
#pragma unroll
                for (int pq = 0; pq < 2; ++pq)
#pragma unroll
                    for (int h = 0; h < 2; ++h)
#pragma unroll
                        for (int mt = 0; mt < 2; ++mt) {
                            int* c = acc1[mt][prp * 4 + pq * 2 + h];
                            mma_s8(c[0], c[1], c[2], c[3],
                                   A1[mt][0], A1[mt][1], A1[mt][2], A1[mt][3],
                                   B1[pq][h * 2], B1[pq][h * 2 + 1]);
                        }
                // phase 2: c2 += A1*B2
#pragma unroll
                for (int pq = 0; pq < 2; ++pq)
#pragma unroll
                    for (int h = 0; h < 2; ++h)
#pragma unroll
                        for (int mt = 0; mt < 2; ++mt) {
                            int* c = acc2[mt][prp * 4 + pq * 2 + h];
                            mma_s8(c[0], c[1], c[2], c[3],
                                   A1[mt][0], A1[mt][1], A1[mt][2], A1[mt][3],
                                   B2[pq][h * 2], B2[pq][h * 2 + 1]);
                        }
                // phase 3: c2 += A2*B1
#pragma unroll
                for (int pq = 0; pq < 2; ++pq)
#pragma unroll
                    for (int h = 0; h < 2; ++h)
#pragma unroll
                        for (int mt = 0; mt < 2; ++mt) {
                            int* c = acc2[mt][prp * 4 + pq * 2 + h];
                            mma_s8(c[0], c[1], c[2], c[3],
                                   A2[mt][0], A2[mt][1], A2[mt][2], A2[mt][3],
                                   B1[pq][h * 2], B1[pq][h * 2 + 1]);
                        }
            }
        }
    }

    // Epilogue: logit = sA*sB*(16384*acc1 + 128*acc2) -> g_LTh[n][m] (fp16)
    float sAv[4];
#pragma unroll
    for (int mt = 0; mt < 2; ++mt)
#pragma unroll
        for (int h = 0; h < 2; ++h)
            sAv[mt * 2 + h] = g_sA[m0 + warp_m * 32 + mt * 16 + g + h * 8];
    float sBv[16];
#pragma unroll
    for (int nt = 0; nt < 8; ++nt)
#pragma unroll
        for (int j = 0; j < 2; ++j)
            sBv[nt * 2 + j] = g_sB[n0 + warp_n * 64 + nt * 8 + 2 * t + j];

#pragma unroll
    for (int mt = 0; mt < 2; ++mt)
#pragma unroll
        for (int nt = 0; nt < 8; ++nt)
#pragma unroll
            for (int r = 0; r < 4; ++r) {
                int m = m0 + warp_m * 32 + mt * 16 + g + ((r >= 2) ? 8 : 0);
                int n = n0 + warp_n * 64 + nt * 8 + 2 * t + (r & 1);
                float val = sAv[mt * 2 + (r >> 1)] * sBv[nt * 2 + (r & 1)] *
                            fmaf(16384.f, (float)acc1[mt][nt][r],
                                 128.f * (float)acc2[mt][nt][r]);
                g_LTh[(size_t)n * MDIM + m] = __float2half(val);
            }
}

// ---------------------------------------------------------------------------
// Kernel 4: gates + linear recurrence, register software-pipelined:
//   chunk c+1's lx/la/xv loads are issued right after chunk c's values are
//   consumed, overlapping global latency with the shuffle scan + drain.
//   Output staging double-buffered (one __syncthreads per chunk, from R12).
// ---------------------------------------------------------------------------
static __device__ __forceinline__ float fast_sigmoid(float x) {
    return __fdividef(1.0f, 1.0f + __expf(-x));
}

__global__ void __launch_bounds__(1024, 1) scan_kernel(
    const float* __restrict__ a_param,
    const int* __restrict__ cu, int ncu,
    float* __restrict__ out) {
    __shared__ float sm[2][CHUNK * 33];
    int tid = threadIdx.x;
    int wid = tid >> 5, lane = tid & 31;
    int dgroup = blockIdx.x, b = blockIdx.y;
    int d = dgroup * 32 + wid;

    const __half* rowLx = g_LTh + (size_t)d * MDIM + (size_t)b * SEQLEN;
    const __half* rowLa = g_LTh + (size_t)(DIM + d) * MDIM + (size_t)b * SEQLEN;
    const float*  rowX  = g_xT  + (size_t)d * MDIM + (size_t)b * SEQLEN;
    float af = log1pf(__expf(a_param[d & 127]));      // softplus, tiled over heads

    // prologue loads for chunk 0
    int s0 = lane * 2;
    float2 lx = __half22float2(*reinterpret_cast<const __half2*>(rowLx + s0));
    float2 la = __half22float2(*reinterpret_cast<const __half2*>(rowLa + s0));
    float2 xv = *reinterpret_cast<const float2*>(rowX + s0);

    float h = 0.0f;
#pragma unroll 1
    for (int c = 0; c < NCHUNK; ++c) {
        int buf = c & 1;

        // consume current values into A/B first...
        float A0, B0, A1, B1;
        {
            float gx = fast_sigmoid(lx.x);
            float ga = fast_sigmoid(la.x);
            float a  = __expf(-8.0f * ga * af);
            float mult = sqrtf(fmaxf(1.0f - a * a, 0.0f));
            B0 = mult * gx * xv.x;
            A0 = a;
            for (int j = 0; j < ncu - 1; ++j) if (s0 == cu[j]) A0 = 0.0f;
        }
        {
            float gx = fast_sigmoid(lx.y);
            float ga = fast_sigmoid(la.y);
            float a  = __expf(-8.0f * ga * af);
            float mult = sqrtf(fmaxf(1.0f - a * a, 0.0f));
            B1 = mult * gx * xv.y;
            A1 = a;
            for (int j = 0; j < ncu - 1; ++j) if (s0 + 1 == cu[j]) A1 = 0.0f;
        }

        // ...then immediately issue next chunk's loads (overlap with scan)
        if (c + 1 < NCHUNK) {
            int s1 = (c + 1) * CHUNK + lane * 2;
            lx = __half22float2(*reinterpret_cast<const __half2*>(rowLx + s1));
            la = __half22float2(*reinterpret_cast<const __half2*>(rowLa + s1));
            xv = *reinterpret_cast<const float2*>(rowX + s1);
            s0 = s1;
        }

        float Ai = A0 * A1;
        float Bi = fmaf(A1, B0, B1);
#pragma unroll
        for (int off = 1; off < 32; off <<= 1) {
            float pa = __shfl_up_sync(0xFFFFFFFFu, Ai, off);
            float pb = __shfl_up_sync(0xFFFFFFFFu, Bi, off);
            if (lane >= off) { Bi = fmaf(Ai, pb, Bi); Ai = Ai * pa; }
        }
        float Ae = __shfl_up_sync(0xFFFFFFFFu, Ai, 1);
        float Be = __shfl_up_sync(0xFFFFFFFFu, Bi, 1);
        if (lane == 0) { Ae = 1.0f; Be = 0.0f; }
        float h_in = fmaf(Ae, h, Be);
        float h0 = fmaf(A0, h_in, B0);
        float h1 = fmaf(A1, h0, B1);
        float At = __shfl_sync(0xFFFFFFFFu, Ai, 31);
        float Bt = __shfl_sync(0xFFFFFFFFu, Bi, 31);
        h = fmaf(At, h, Bt);

        sm[buf][(2 * lane) * 33 + wid]     = h0;
        sm[buf][(2 * lane + 1) * 33 + wid] = h1;
        __syncthreads();
        {
            size_t obase = ((size_t)b * SEQLEN + (size_t)c * CHUNK) * DIM + dgroup * 32;
#pragma unroll
            for (int rep = 0; rep < 2; ++rep) {
                int i = tid + rep * 1024;
                int tt = i >> 5, dd = i & 31;
                out[obase + (size_t)tt * DIM + dd] = sm[buf][tt * 33 + dd];
            }
        }
        // no second sync: alternate buffer + next chunk's sync covers reuse.
    }
}

// ---------------------------------------------------------------------------
// Launch
// ---------------------------------------------------------------------------
extern "C" void kernel_launch(void* const* d_in, const int* in_sizes, int n_in,
                              void* d_out, int out_size) {
    const float* x    = (const float*)d_in[0];
    const float* cw   = (const float*)d_in[1];
    const float* wig  = (const float*)d_in[2];
    const float* wag  = (const float*)d_in[3];
    const float* ap   = (const float*)d_in[4];
    const int*   cu   = (const int*)d_in[5];
    int ncu = in_sizes[5];
    float* out = (float*)d_out;

    quant_kernel<<<MDIM + NDIM, 256>>>(x, cw, wig, wag);
    xT_kernel<<<dim3(DIM / 32, MDIM / 32), dim3(32, 8)>>>();

    cudaFuncSetAttribute(gemm_kernel, cudaFuncAttributeMaxDynamicSharedMemorySize,
                         GEMM_SMEM);
    gemm_kernel<<<dim3(NDIM / 128, MDIM / 128), 256, GEMM_SMEM>>>();

    scan_kernel<<<dim3(DIM / 32, BSZ), 1024>>>(ap, cu, ncu, out);
}